// round 1
// baseline (speedup 1.0000x reference)
#include <cuda_runtime.h>

// ---------------------------------------------------------------------------
// NonLocalMSA: x[16,64,256,256] fp32
//  qkv = 1x1(w_qkv) -> dw3x3 depthwise -> window attention (8x8 windows,
//  token = whole 32x32 window, head h = rows [4h,4h+4) of window) -> 1x1 proj.
// Pipeline: K1 qkv+dw fused | K2 sim partials | K3 softmax | K4 attn@V | K5 proj
// ---------------------------------------------------------------------------

#define HW 65536  // 256*256

// Scratch (device globals: allocation-free rule)
__device__ float g_qkv[16ull * 192 * 256 * 256];  // 805 MB: q[0:64),k[64:128),v[128:192)
__device__ float g_av [16ull *  64 * 256 * 256];  // 268 MB: attention output (spatial)
__device__ float g_sim[512ull * 64 * 64];         // 8 MB: partial sims per (b,h,r)
__device__ float g_attn[128ull * 64 * 64];        // 2 MB: softmax probs per (b,h)

// ===========================================================================
// K1: fused 1x1 qkv projection + 3x3 depthwise conv.
// Block = 16x16 spatial tile (halo 18x18), loops over 4 chunks of 48 out-chans.
// ===========================================================================
#define HPAD 328   // 18*18=324 padded to mult-of-4 for float4
#define OC 48

extern __shared__ float k1smem[];

__global__ __launch_bounds__(512) void k1_qkv_dw(
    const float* __restrict__ x, const float* __restrict__ wqkv,
    const float* __restrict__ wdw)
{
    float* sx  = k1smem;             // [64][HPAD]
    float* sq  = sx  + 64 * HPAD;    // [OC][HPAD]
    float* sw  = sq  + OC * HPAD;    // [OC][64]
    float* sdw = sw  + OC * 64;      // [OC][9]

    const int b = blockIdx.z, ty = blockIdx.y, tx = blockIdx.x;
    const int tid = threadIdx.x;
    const float* xb = x + (size_t)b * 64 * HW;

    // Load x tile with 1-halo, zero padded (1x1 has no bias -> qkv(0)=0, so
    // zero-padding x exactly reproduces the dw conv's zero padding on qkv).
    for (int idx = tid; idx < 64 * 324; idx += 512) {
        int c = idx / 324, p = idx - c * 324;
        int iy = p / 18, ix = p - iy * 18;
        int gy = ty * 16 - 1 + iy, gx = tx * 16 - 1 + ix;
        float v = 0.f;
        if ((unsigned)gy < 256u && (unsigned)gx < 256u)
            v = xb[c * HW + gy * 256 + gx];
        sx[c * HPAD + p] = v;
    }

    for (int ocb = 0; ocb < 4; ocb++) {
        const int o0 = ocb * OC;
        __syncthreads();  // protect sw/sq reuse (also orders sx after load)
        for (int idx = tid; idx < OC * 64; idx += 512)
            sw[idx] = wqkv[(o0 + (idx >> 6)) * 64 + (idx & 63)];
        for (int idx = tid; idx < OC * 9; idx += 512)
            sdw[idx] = wdw[(o0 + idx / 9) * 9 + idx % 9];
        __syncthreads();

        // 1x1 over full halo tile: 12 o-groups x 81 p-groups, 4x4 register tile
        for (int u = tid; u < 12 * 81; u += 512) {
            int og = u / 81, pg = u - og * 81;
            int ob = og * 4, pb = pg * 4;
            float a00=0,a01=0,a02=0,a03=0, a10=0,a11=0,a12=0,a13=0;
            float a20=0,a21=0,a22=0,a23=0, a30=0,a31=0,a32=0,a33=0;
            const float* swb = sw + ob * 64;
            #pragma unroll 8
            for (int c = 0; c < 64; c++) {
                float4 xv = *(const float4*)&sx[c * HPAD + pb];
                float w0 = swb[c], w1 = swb[64 + c], w2 = swb[128 + c], w3 = swb[192 + c];
                a00 += w0*xv.x; a01 += w0*xv.y; a02 += w0*xv.z; a03 += w0*xv.w;
                a10 += w1*xv.x; a11 += w1*xv.y; a12 += w1*xv.z; a13 += w1*xv.w;
                a20 += w2*xv.x; a21 += w2*xv.y; a22 += w2*xv.z; a23 += w2*xv.w;
                a30 += w3*xv.x; a31 += w3*xv.y; a32 += w3*xv.z; a33 += w3*xv.w;
            }
            *(float4*)&sq[(ob+0) * HPAD + pb] = make_float4(a00,a01,a02,a03);
            *(float4*)&sq[(ob+1) * HPAD + pb] = make_float4(a10,a11,a12,a13);
            *(float4*)&sq[(ob+2) * HPAD + pb] = make_float4(a20,a21,a22,a23);
            *(float4*)&sq[(ob+3) * HPAD + pb] = make_float4(a30,a31,a32,a33);
        }
        __syncthreads();

        // depthwise 3x3 on the tile interior; write to g_qkv
        for (int idx = tid; idx < OC * 256; idx += 512) {
            int o = idx >> 8, p = idx & 255;
            int iy = p >> 4, ix = p & 15;
            const float* q = &sq[o * HPAD + iy * 18 + ix];  // halo coords
            const float* d = &sdw[o * 9];
            float acc = d[0]*q[0]  + d[1]*q[1]  + d[2]*q[2]
                      + d[3]*q[18] + d[4]*q[19] + d[5]*q[20]
                      + d[6]*q[36] + d[7]*q[37] + d[8]*q[38];
            int gy = ty * 16 + iy, gx = tx * 16 + ix;
            g_qkv[(((size_t)b * 192 + o0 + o) * 256 + gy) * 256 + gx] = acc;
        }
    }
}

// ===========================================================================
// K2: sim partials. Block = (b,h,r). C[64,64] += A[64,2048] * B^T.
// K-dim enumerated as 32 chunks of (2 channels x 32 cols) for coalescing.
// ===========================================================================
__global__ __launch_bounds__(256) void k2_sim()
{
    __shared__ float As[64 * 68];  // [k][i]
    __shared__ float Bs[64 * 68];  // [k][j]
    const int blk = blockIdx.x;
    const int r = blk & 3, h = (blk >> 2) & 7, b = blk >> 5;
    const int tid = threadIdx.x, ti = tid >> 4, tj = tid & 15;
    const int yoff = h * 4 + r;

    const float* qbase = g_qkv + (size_t)b * 192 * HW;
    const float* kbase = qbase + (size_t)64 * HW;

    float a00=0,a01=0,a02=0,a03=0, a10=0,a11=0,a12=0,a13=0;
    float a20=0,a21=0,a22=0,a23=0, a30=0,a31=0,a32=0,a33=0;

    for (int kc = 0; kc < 32; kc++) {
        __syncthreads();
        for (int idx = tid; idx < 4096; idx += 256) {
            int t = idx >> 6, kl = idx & 63;
            int chp = kl >> 5, col = kl & 31;
            int y = (t >> 3) * 32 + yoff;
            int xx = (t & 7) * 32 + col;
            size_t off = (size_t)(kc * 2 + chp) * HW + y * 256 + xx;
            As[kl * 68 + t] = qbase[off];
            Bs[kl * 68 + t] = kbase[off];
        }
        __syncthreads();
        #pragma unroll 8
        for (int kk = 0; kk < 64; kk++) {
            float4 av = *(const float4*)&As[kk * 68 + ti * 4];
            float4 bv = *(const float4*)&Bs[kk * 68 + tj * 4];
            a00 += av.x*bv.x; a01 += av.x*bv.y; a02 += av.x*bv.z; a03 += av.x*bv.w;
            a10 += av.y*bv.x; a11 += av.y*bv.y; a12 += av.y*bv.z; a13 += av.y*bv.w;
            a20 += av.z*bv.x; a21 += av.z*bv.y; a22 += av.z*bv.z; a23 += av.z*bv.w;
            a30 += av.w*bv.x; a31 += av.w*bv.y; a32 += av.w*bv.z; a33 += av.w*bv.w;
        }
    }
    float* so = g_sim + (size_t)blk * 4096;
    so[(ti*4+0)*64 + tj*4+0]=a00; so[(ti*4+0)*64 + tj*4+1]=a01; so[(ti*4+0)*64 + tj*4+2]=a02; so[(ti*4+0)*64 + tj*4+3]=a03;
    so[(ti*4+1)*64 + tj*4+0]=a10; so[(ti*4+1)*64 + tj*4+1]=a11; so[(ti*4+1)*64 + tj*4+2]=a12; so[(ti*4+1)*64 + tj*4+3]=a13;
    so[(ti*4+2)*64 + tj*4+0]=a20; so[(ti*4+2)*64 + tj*4+1]=a21; so[(ti*4+2)*64 + tj*4+2]=a22; so[(ti*4+2)*64 + tj*4+3]=a23;
    so[(ti*4+3)*64 + tj*4+0]=a30; so[(ti*4+3)*64 + tj*4+1]=a31; so[(ti*4+3)*64 + tj*4+2]=a32; so[(ti*4+3)*64 + tj*4+3]=a33;
}

// ===========================================================================
// K3: softmax over j(64): attn = softmax(scale * sum_r sim + pos_emb)
// ===========================================================================
__global__ __launch_bounds__(128) void k3_softmax(const float* __restrict__ pos)
{
    const float SCALE = 0.011048543456039806f;  // 8192^-0.5
    int row = blockIdx.x * 4 + (threadIdx.x >> 5);  // (b*8+h)*64 + i
    int lane = threadIdx.x & 31;
    int bh = row >> 6, i = row & 63;
    const float* s0 = g_sim + (size_t)bh * 4 * 4096 + i * 64;
    const float* pe = pos + (bh & 7) * 4096 + i * 64;
    float v1 = SCALE * (s0[lane]      + s0[4096 + lane]      + s0[8192 + lane]      + s0[12288 + lane])      + pe[lane];
    float v2 = SCALE * (s0[lane + 32] + s0[4096 + lane + 32] + s0[8192 + lane + 32] + s0[12288 + lane + 32]) + pe[lane + 32];
    float m = fmaxf(v1, v2);
    #pragma unroll
    for (int o = 16; o; o >>= 1) m = fmaxf(m, __shfl_xor_sync(0xffffffffu, m, o));
    float e1 = __expf(v1 - m), e2 = __expf(v2 - m);
    float s = e1 + e2;
    #pragma unroll
    for (int o = 16; o; o >>= 1) s += __shfl_xor_sync(0xffffffffu, s, o);
    float inv = 1.f / s;
    g_attn[(size_t)row * 64 + lane]      = e1 * inv;
    g_attn[(size_t)row * 64 + lane + 32] = e2 * inv;
}

// ===========================================================================
// K4: out = attn @ V per (b,h,r), result scattered to spatial layout g_av.
// Loops 32 chunks of (2 channels x 32 cols); C chunk = [64 tok][64 cc].
// ===========================================================================
__global__ __launch_bounds__(256) void k4_av()
{
    __shared__ float At[64 * 68];  // attn transposed: [j][t]
    __shared__ float Vs[64 * 68];  // [j][cc]
    const int blk = blockIdx.x;
    const int r = blk & 3, h = (blk >> 2) & 7, b = blk >> 5;
    const int tid = threadIdx.x, ti = tid >> 4, tj = tid & 15;
    const int yoff = h * 4 + r;

    const float* ap = g_attn + (size_t)(b * 8 + h) * 4096;
    for (int idx = tid; idx < 4096; idx += 256) {
        int t = idx >> 6, j = idx & 63;
        At[j * 68 + t] = ap[t * 64 + j];
    }
    const float* vbase = g_qkv + ((size_t)b * 192 + 128) * HW;
    float* ob = g_av + (size_t)b * 64 * HW;

    for (int cp = 0; cp < 32; cp++) {
        __syncthreads();  // protects At (first iter) and Vs (later iters)
        for (int idx = tid; idx < 4096; idx += 256) {
            int j = idx >> 6, kl = idx & 63;
            int chp = kl >> 5, col = kl & 31;
            int y = (j >> 3) * 32 + yoff;
            int xx = (j & 7) * 32 + col;
            Vs[j * 68 + kl] = vbase[(size_t)(cp * 2 + chp) * HW + y * 256 + xx];
        }
        __syncthreads();
        float a00=0,a01=0,a02=0,a03=0, a10=0,a11=0,a12=0,a13=0;
        float a20=0,a21=0,a22=0,a23=0, a30=0,a31=0,a32=0,a33=0;
        #pragma unroll 8
        for (int kk = 0; kk < 64; kk++) {
            float4 av = *(const float4*)&At[kk * 68 + ti * 4];
            float4 vv = *(const float4*)&Vs[kk * 68 + tj * 4];
            a00 += av.x*vv.x; a01 += av.x*vv.y; a02 += av.x*vv.z; a03 += av.x*vv.w;
            a10 += av.y*vv.x; a11 += av.y*vv.y; a12 += av.y*vv.z; a13 += av.y*vv.w;
            a20 += av.z*vv.x; a21 += av.z*vv.y; a22 += av.z*vv.z; a23 += av.z*vv.w;
            a30 += av.w*vv.x; a31 += av.w*vv.y; a32 += av.w*vv.z; a33 += av.w*vv.w;
        }
        int cc0 = tj * 4, chp = cc0 >> 5, col0 = cc0 & 31;
        size_t cbase = (size_t)(cp * 2 + chp) * HW;
        float4 rows[4] = { make_float4(a00,a01,a02,a03), make_float4(a10,a11,a12,a13),
                           make_float4(a20,a21,a22,a23), make_float4(a30,a31,a32,a33) };
        #pragma unroll
        for (int ii = 0; ii < 4; ii++) {
            int t = ti * 4 + ii;
            int y = (t >> 3) * 32 + yoff;
            int xx = (t & 7) * 32 + col0;
            *(float4*)&ob[cbase + y * 256 + xx] = rows[ii];
        }
    }
}

// ===========================================================================
// K5: 1x1 projection + bias. Block = 64 spatial positions; [64x64] GEMM.
// ===========================================================================
__global__ __launch_bounds__(256) void k5_proj(
    const float* __restrict__ wp, const float* __restrict__ bp,
    float* __restrict__ out)
{
    __shared__ float Ws[64 * 68];  // [c][o]
    __shared__ float Xs[64 * 68];  // [c][p]
    const int blk = blockIdx.x;          // 16384 = 16 b * 256 y * 4 xq
    const int b = blk >> 10;
    const int rem = blk & 1023;
    const int y = rem >> 2, x0 = (rem & 3) << 6;
    const int tid = threadIdx.x, ti = tid >> 4, tj = tid & 15;

    const float* ib = g_av + (size_t)b * 64 * HW + y * 256 + x0;
    for (int idx = tid; idx < 4096; idx += 256) {
        int o = idx >> 6, c = idx & 63;
        Ws[c * 68 + o] = wp[o * 64 + c];
    }
    for (int idx = tid; idx < 4096; idx += 256) {
        int c = idx >> 6, p = idx & 63;
        Xs[c * 68 + p] = ib[(size_t)c * HW + p];
    }
    __syncthreads();
    float a00=0,a01=0,a02=0,a03=0, a10=0,a11=0,a12=0,a13=0;
    float a20=0,a21=0,a22=0,a23=0, a30=0,a31=0,a32=0,a33=0;
    #pragma unroll 8
    for (int c = 0; c < 64; c++) {
        float4 wv = *(const float4*)&Ws[c * 68 + ti * 4];
        float4 xv = *(const float4*)&Xs[c * 68 + tj * 4];
        a00 += wv.x*xv.x; a01 += wv.x*xv.y; a02 += wv.x*xv.z; a03 += wv.x*xv.w;
        a10 += wv.y*xv.x; a11 += wv.y*xv.y; a12 += wv.y*xv.z; a13 += wv.y*xv.w;
        a20 += wv.z*xv.x; a21 += wv.z*xv.y; a22 += wv.z*xv.z; a23 += wv.z*xv.w;
        a30 += wv.w*xv.x; a31 += wv.w*xv.y; a32 += wv.w*xv.z; a33 += wv.w*xv.w;
    }
    float* op = out + (size_t)b * 64 * HW + y * 256 + x0 + tj * 4;
    float b0 = bp[ti*4+0], b1 = bp[ti*4+1], b2 = bp[ti*4+2], b3 = bp[ti*4+3];
    *(float4*)&op[(size_t)(ti*4+0) * HW] = make_float4(a00+b0, a01+b0, a02+b0, a03+b0);
    *(float4*)&op[(size_t)(ti*4+1) * HW] = make_float4(a10+b1, a11+b1, a12+b1, a13+b1);
    *(float4*)&op[(size_t)(ti*4+2) * HW] = make_float4(a20+b2, a21+b2, a22+b2, a23+b2);
    *(float4*)&op[(size_t)(ti*4+3) * HW] = make_float4(a30+b3, a31+b3, a32+b3, a33+b3);
}

// ===========================================================================
extern "C" void kernel_launch(void* const* d_in, const int* in_sizes, int n_in,
                              void* d_out, int out_size)
{
    const float* x     = (const float*)d_in[0];
    const float* wqkv  = (const float*)d_in[1];
    const float* wdw   = (const float*)d_in[2];
    const float* wproj = (const float*)d_in[3];
    const float* bproj = (const float*)d_in[4];
    const float* pos   = (const float*)d_in[5];
    float* out = (float*)d_out;

    const int smem1 = (64 * HPAD + OC * HPAD + OC * 64 + OC * 9) * 4;  // 160960 B
    cudaFuncSetAttribute(k1_qkv_dw, cudaFuncAttributeMaxDynamicSharedMemorySize, smem1);

    k1_qkv_dw<<<dim3(16, 16, 16), 512, smem1>>>(x, wqkv, wdw);
    k2_sim<<<512, 256>>>();
    k3_softmax<<<2048, 128>>>(pos);
    k4_av<<<512, 256>>>();
    k5_proj<<<16384, 256>>>(wproj, bproj, out);
}